// round 1
// baseline (speedup 1.0000x reference)
#include <cuda_runtime.h>
#include <math.h>

#define VOCAB 50257
#define EMBED 128
#define HIDDEN 128
#define NCLASS 4
#define BB 256
#define TT 512

// Scratch for x_proj[t][b][h] : 512*256*128 floats = 64MB (device global, no runtime alloc)
__device__ float g_xp[TT * BB * HIDDEN];

__device__ __forceinline__ float fast_tanh(float x) {
    // tanh(x) = 1 - 2/(exp(2x)+1); clamp so __expf stays finite & __fdividef safe
    x = fminf(fmaxf(x, -15.0f), 15.0f);
    float e = __expf(2.0f * x);
    return 1.0f - __fdividef(2.0f, e + 1.0f);
}

// ---------------------------------------------------------------------------
// Kernel 1: x_proj[t,b,:] = emb[x[b,t],:] @ W_ih^T + (b_ih + b_hh)
// warp-per-row; W_ih^T staged in shared; activations broadcast via shfl.
// ---------------------------------------------------------------------------
__global__ void __launch_bounds__(256) xproj_kernel(
    const int* __restrict__ x, const float* __restrict__ emb,
    const float* __restrict__ W_ih, const float* __restrict__ b_ih,
    const float* __restrict__ b_hh)
{
    extern __shared__ float sh[];  // Wt[e][h] = W_ih[h][e], 128*128 floats
    const int tid = threadIdx.x;
    for (int i = tid; i < EMBED * HIDDEN; i += 256) {
        int h = i >> 7, e = i & 127;
        sh[e * HIDDEN + h] = W_ih[i];
    }
    __syncthreads();

    const int lane = tid & 31;
    const int gwarp = blockIdx.x * 8 + (tid >> 5);
    const int nwarps = gridDim.x * 8;

    float4 bias;
    bias.x = b_ih[lane * 4 + 0] + b_hh[lane * 4 + 0];
    bias.y = b_ih[lane * 4 + 1] + b_hh[lane * 4 + 1];
    bias.z = b_ih[lane * 4 + 2] + b_hh[lane * 4 + 2];
    bias.w = b_ih[lane * 4 + 3] + b_hh[lane * 4 + 3];

    const float4* sh4 = (const float4*)sh;

    for (int r = gwarp; r < BB * TT; r += nwarps) {
        const int token = x[r];
        const float4 a = ((const float4*)(emb + (size_t)token * EMBED))[lane];
        float4 acc = bias;
        #pragma unroll 8
        for (int src = 0; src < 32; ++src) {
            float v0 = __shfl_sync(0xffffffffu, a.x, src);
            float v1 = __shfl_sync(0xffffffffu, a.y, src);
            float v2 = __shfl_sync(0xffffffffu, a.z, src);
            float v3 = __shfl_sync(0xffffffffu, a.w, src);
            float4 w0 = sh4[(src * 4 + 0) * 32 + lane];
            float4 w1 = sh4[(src * 4 + 1) * 32 + lane];
            float4 w2 = sh4[(src * 4 + 2) * 32 + lane];
            float4 w3 = sh4[(src * 4 + 3) * 32 + lane];
            acc.x = fmaf(v0, w0.x, acc.x); acc.y = fmaf(v0, w0.y, acc.y);
            acc.z = fmaf(v0, w0.z, acc.z); acc.w = fmaf(v0, w0.w, acc.w);
            acc.x = fmaf(v1, w1.x, acc.x); acc.y = fmaf(v1, w1.y, acc.y);
            acc.z = fmaf(v1, w1.z, acc.z); acc.w = fmaf(v1, w1.w, acc.w);
            acc.x = fmaf(v2, w2.x, acc.x); acc.y = fmaf(v2, w2.y, acc.y);
            acc.z = fmaf(v2, w2.z, acc.z); acc.w = fmaf(v2, w2.w, acc.w);
            acc.x = fmaf(v3, w3.x, acc.x); acc.y = fmaf(v3, w3.y, acc.y);
            acc.z = fmaf(v3, w3.z, acc.z); acc.w = fmaf(v3, w3.w, acc.w);
        }
        const int b = r >> 9;        // r = b*T + t
        const int t = r & (TT - 1);
        ((float4*)(g_xp + (size_t)t * (BB * HIDDEN) + b * HIDDEN))[lane] = acc;
    }
}

// ---------------------------------------------------------------------------
// Kernel 2: recurrence. 128 CTAs x 128 threads. Each CTA owns 2 batch rows;
// each row is computed by 2 warps splitting K in halves (reduce via SMEM).
// W_hh^T staged in shared. No cross-CTA sync needed (rows independent).
// ---------------------------------------------------------------------------
__global__ void __launch_bounds__(128) rnn_kernel(
    const float* __restrict__ h0, const float* __restrict__ W_hh,
    float* __restrict__ out_hidden)
{
    extern __shared__ float sh[];
    float* shW = sh;            // Wt[k*128 + j] = W_hh[j*128 + k]  (16384 floats)
    float* shH = sh + 16384;    // h, 2 rows x 128
    float* shP = shH + 256;     // partials, 2 rows x 128

    const int tid = threadIdx.x;
    for (int i = tid; i < HIDDEN * HIDDEN; i += 128) {
        int j = i >> 7, k = i & 127;
        shW[k * 128 + j] = W_hh[i];
    }
    for (int i = tid; i < 256; i += 128)
        shH[i] = h0[blockIdx.x * 256 + i];
    __syncthreads();

    const int lane = tid & 31;
    const int warp = tid >> 5;   // 0..3
    const int row  = warp >> 1;  // local row 0/1
    const int half = warp & 1;   // K half
    const int grow = blockIdx.x * 2 + row;

    const float4* shW4 = (const float4*)shW;
    const float4* shH4 = (const float4*)(shH + row * 128);
    const float*  xp_base = g_xp + (size_t)grow * HIDDEN + lane * 4;

    for (int t = 0; t < TT; ++t) {
        float4 xv = make_float4(0.f, 0.f, 0.f, 0.f);
        if (half == 0)
            xv = *(const float4*)(xp_base + (size_t)t * (BB * HIDDEN));

        float4 acc = make_float4(0.f, 0.f, 0.f, 0.f);
        #pragma unroll
        for (int k4 = 0; k4 < 16; ++k4) {
            float4 hv = shH4[half * 16 + k4];
            int k = half * 64 + k4 * 4;
            float4 w0 = shW4[(k + 0) * 32 + lane];
            float4 w1 = shW4[(k + 1) * 32 + lane];
            float4 w2 = shW4[(k + 2) * 32 + lane];
            float4 w3 = shW4[(k + 3) * 32 + lane];
            acc.x = fmaf(hv.x, w0.x, acc.x); acc.y = fmaf(hv.x, w0.y, acc.y);
            acc.z = fmaf(hv.x, w0.z, acc.z); acc.w = fmaf(hv.x, w0.w, acc.w);
            acc.x = fmaf(hv.y, w1.x, acc.x); acc.y = fmaf(hv.y, w1.y, acc.y);
            acc.z = fmaf(hv.y, w1.z, acc.z); acc.w = fmaf(hv.y, w1.w, acc.w);
            acc.x = fmaf(hv.z, w2.x, acc.x); acc.y = fmaf(hv.z, w2.y, acc.y);
            acc.z = fmaf(hv.z, w2.z, acc.z); acc.w = fmaf(hv.z, w2.w, acc.w);
            acc.x = fmaf(hv.w, w3.x, acc.x); acc.y = fmaf(hv.w, w3.y, acc.y);
            acc.z = fmaf(hv.w, w3.z, acc.z); acc.w = fmaf(hv.w, w3.w, acc.w);
        }

        if (half == 1)
            ((float4*)(shP + row * 128))[lane] = acc;
        __syncthreads();
        if (half == 0) {
            float4 p = ((const float4*)(shP + row * 128))[lane];
            float4 s;
            s.x = fast_tanh(xv.x + acc.x + p.x);
            s.y = fast_tanh(xv.y + acc.y + p.y);
            s.z = fast_tanh(xv.z + acc.z + p.z);
            s.w = fast_tanh(xv.w + acc.w + p.w);
            ((float4*)(shH + row * 128))[lane] = s;
        }
        __syncthreads();
    }

    if (half == 0)
        ((float4*)(out_hidden + (size_t)grow * HIDDEN))[lane] =
            ((const float4*)(shH + row * 128))[lane];
}

// ---------------------------------------------------------------------------
// Kernel 3: MLP head. One CTA per batch row.
// ---------------------------------------------------------------------------
__global__ void __launch_bounds__(256) head_kernel(
    const float* __restrict__ hidden, const float* __restrict__ W1,
    const float* __restrict__ b1, const float* __restrict__ W2,
    const float* __restrict__ b2, float* __restrict__ logits)
{
    __shared__ float shH[HIDDEN];
    __shared__ float shM[2 * HIDDEN];
    const int b = blockIdx.x, tid = threadIdx.x;
    if (tid < HIDDEN) shH[tid] = hidden[(size_t)b * HIDDEN + tid];
    __syncthreads();

    float acc = b1[tid];
    const float4* w4 = (const float4*)(W1 + (size_t)tid * HIDDEN);
    const float4* h4 = (const float4*)shH;
    #pragma unroll 8
    for (int k4 = 0; k4 < 32; ++k4) {
        float4 w = w4[k4];
        float4 h = h4[k4];
        acc = fmaf(w.x, h.x, acc);
        acc = fmaf(w.y, h.y, acc);
        acc = fmaf(w.z, h.z, acc);
        acc = fmaf(w.w, h.w, acc);
    }
    shM[tid] = fmaxf(acc, 0.0f);
    __syncthreads();

    if (tid < NCLASS) {
        float a = b2[tid];
        const float* w2 = W2 + (size_t)tid * (2 * HIDDEN);
        #pragma unroll 8
        for (int k = 0; k < 2 * HIDDEN; ++k)
            a = fmaf(shM[k], w2[k], a);
        logits[(size_t)b * NCLASS + tid] = a;
    }
}

// ---------------------------------------------------------------------------
extern "C" void kernel_launch(void* const* d_in, const int* in_sizes, int n_in,
                              void* d_out, int out_size)
{
    const int*   x    = (const int*)  d_in[0];
    const float* h0   = (const float*)d_in[1];
    const float* emb  = (const float*)d_in[2];
    const float* W_ih = (const float*)d_in[3];
    const float* W_hh = (const float*)d_in[4];
    const float* b_ih = (const float*)d_in[5];
    const float* b_hh = (const float*)d_in[6];
    const float* W1   = (const float*)d_in[7];
    const float* b1   = (const float*)d_in[8];
    const float* W2   = (const float*)d_in[9];
    const float* b2   = (const float*)d_in[10];

    float* out    = (float*)d_out;
    float* logits = out;                 // [256*4]
    float* hidden = out + BB * NCLASS;   // [256*128]

    const int smem1 = EMBED * HIDDEN * sizeof(float);                  // 64KB
    const int smem2 = (HIDDEN * HIDDEN + 256 + 256) * sizeof(float);   // ~66KB
    cudaFuncSetAttribute(xproj_kernel, cudaFuncAttributeMaxDynamicSharedMemorySize, smem1);
    cudaFuncSetAttribute(rnn_kernel,   cudaFuncAttributeMaxDynamicSharedMemorySize, smem2);

    xproj_kernel<<<444, 256, smem1>>>(x, emb, W_ih, b_ih, b_hh);
    rnn_kernel<<<BB / 2, 128, smem2>>>(h0, W_hh, hidden);
    head_kernel<<<BB, 256>>>(hidden, W1, b1, W2, b2, logits);
}

// round 2
// speedup vs baseline: 2.2205x; 2.2205x over previous
#include <cuda_runtime.h>
#include <math.h>

#define VOCAB   50257
#define EMBED   128
#define HIDDEN  128
#define NCLASS  4
#define BB      256
#define TT      512
#define NTOK    (BB * TT)          // 131072

// x_proj scratch [t][b][h] : 64MB device global (no runtime alloc)
__device__ float g_xp[TT * BB * HIDDEN];

// ---------------------------------------------------------------- helpers
__device__ __forceinline__ unsigned smem_u32(const void* p) {
    return (unsigned)__cvta_generic_to_shared(p);
}
__device__ __forceinline__ void cp_async4(void* dst, const void* src) {
    asm volatile("cp.async.ca.shared.global [%0], [%1], 4;"
                 :: "r"(smem_u32(dst)), "l"(src));
}
__device__ __forceinline__ void cp_commit() {
    asm volatile("cp.async.commit_group;");
}
__device__ __forceinline__ void cp_wait1() {
    asm volatile("cp.async.wait_group 1;");
}
__device__ __forceinline__ void cp_wait0() {
    asm volatile("cp.async.wait_group 0;");
}
// packed dual fp32 FMA (sm_103a f32x2 pipe)
__device__ __forceinline__ unsigned long long
fma2(unsigned long long a, unsigned long long b, unsigned long long c) {
    unsigned long long d;
    asm("fma.rn.f32x2 %0, %1, %2, %3;" : "=l"(d) : "l"(a), "l"(b), "l"(c));
    return d;
}
__device__ __forceinline__ float2 unpack2(unsigned long long v) {
    float2 r;
    asm("mov.b64 {%0, %1}, %2;" : "=f"(r.x), "=f"(r.y) : "l"(v));
    return r;
}
__device__ __forceinline__ float fast_tanh(float x) {
    x = fminf(fmaxf(x, -15.0f), 15.0f);
    float e = __expf(2.0f * x);
    return 1.0f - __fdividef(2.0f, e + 1.0f);
}

// ---------------------------------------------------------------------------
// Kernel 1: x_proj[t,b,:] = emb[x[b,t],:] @ W_ih^T + (b_ih + b_hh)
// 148 CTAs x 256 threads. Thread owns one output (out = tid&127) with the full
// weight row in registers (64 x f32x2). Warps 0-3 handle even token slots,
// warps 4-7 odd slots. Embeddings staged 16 tokens at a time via cp.async
// (double buffered); activation reads are CTA-wide broadcast LDS.128.
// ---------------------------------------------------------------------------
#define XP_GRID  148
#define XP_TPC   886            // tokens per CTA (148*886 >= 131072)
#define XP_CH    16             // tokens per staged chunk
#define XP_NC    ((XP_TPC + XP_CH - 1) / XP_CH)   // 56

__global__ void __launch_bounds__(256, 1) xproj_kernel(
    const int* __restrict__ x, const float* __restrict__ emb,
    const float* __restrict__ W_ih, const float* __restrict__ b_ih,
    const float* __restrict__ b_hh)
{
    extern __shared__ float sh[];
    int*   s_ids = (int*)sh;                 // 896 ids
    float* s_buf = sh + 896;                 // 2 x (16*128) floats = 16KB

    const int tid  = threadIdx.x;
    const int out  = tid & 127;
    const int half = tid >> 7;               // token-slot subgroup
    const int r0   = blockIdx.x * XP_TPC;

    // stage token ids (pad with 0 -> emb pad row is zero, harmless)
    for (int i = tid; i < 896; i += 256) {
        int r = r0 + i;
        s_ids[i] = (i < XP_TPC && r < NTOK) ? x[r] : 0;
    }

    // stage W_ih -> per-thread registers via 4 coalesced shared passes
    unsigned long long w2[64];
    for (int p = 0; p < 4; ++p) {
        for (int i = tid; i < 32 * 128; i += 256)
            s_buf[i] = W_ih[p * 32 * 128 + i];
        __syncthreads();
        if ((out >> 5) == p) {
            const unsigned long long* row =
                (const unsigned long long*)(s_buf + (out & 31) * 128);
            #pragma unroll
            for (int k = 0; k < 64; ++k) w2[k] = row[k];
        }
        __syncthreads();
    }
    const float bias = b_ih[out] + b_hh[out];

    // prologue: stage chunk 0
    {
        float* dst = s_buf;
        #pragma unroll
        for (int j = 0; j < 8; ++j) {
            int slot = j * 2 + half;
            int id = s_ids[slot];
            cp_async4(dst + slot * 128 + out, emb + (size_t)id * EMBED + out);
        }
        cp_commit();
    }

    for (int c = 0; c < XP_NC; ++c) {
        // stage chunk c+1 into the other buffer
        if (c + 1 < XP_NC) {
            float* dst = s_buf + ((c + 1) & 1) * (XP_CH * 128);
            #pragma unroll
            for (int j = 0; j < 8; ++j) {
                int slot = j * 2 + half;
                int id = s_ids[(c + 1) * XP_CH + slot];
                cp_async4(dst + slot * 128 + out, emb + (size_t)id * EMBED + out);
            }
            cp_commit();
            cp_wait1();
        } else {
            cp_wait0();
        }
        __syncthreads();

        const float* buf = s_buf + (c & 1) * (XP_CH * 128);
        for (int j = 0; j < 8; ++j) {
            int slot = half * 8 + j;
            int i_tok = c * XP_CH + slot;
            int r = r0 + i_tok;
            if (i_tok < XP_TPC && r < NTOK) {
                const ulonglong2* a4 = (const ulonglong2*)(buf + slot * 128);
                unsigned long long acc0 = 0, acc1 = 0, acc2a = 0, acc3 = 0;
                #pragma unroll
                for (int k4 = 0; k4 < 32; ++k4) {
                    ulonglong2 a = a4[k4];
                    if (k4 & 1) {
                        acc2a = fma2(w2[k4 * 2],     a.x, acc2a);
                        acc3  = fma2(w2[k4 * 2 + 1], a.y, acc3);
                    } else {
                        acc0  = fma2(w2[k4 * 2],     a.x, acc0);
                        acc1  = fma2(w2[k4 * 2 + 1], a.y, acc1);
                    }
                }
                float2 u0 = unpack2(acc0), u1 = unpack2(acc1);
                float2 u2 = unpack2(acc2a), u3 = unpack2(acc3);
                float s = ((u0.x + u0.y) + (u1.x + u1.y)) +
                          ((u2.x + u2.y) + (u3.x + u3.y)) + bias;
                int b = r >> 9, t = r & (TT - 1);
                g_xp[((size_t)t * BB + b) * HIDDEN + out] = s;
            }
        }
        __syncthreads();
    }
}

// ---------------------------------------------------------------------------
// Kernel 2: recurrence. 128 CTAs x 256 threads (1 CTA/SM). CTA owns rows
// (2*blk, 2*blk+1); thread owns one (row, output): row = tid>>7, out = tid&127.
// W_hh register-resident (64 f32x2/thread). h double-buffered in shared ->
// ONE __syncthreads per step. xp prefetched one step ahead.
// ---------------------------------------------------------------------------
__global__ void __launch_bounds__(256, 1) rnn_kernel(
    const float* __restrict__ h0, const float* __restrict__ W_hh,
    float* __restrict__ out_hidden)
{
    extern __shared__ float sh[];
    float* s_h   = sh;            // [2 bufs][2 rows][128]
    float* s_stg = sh + 512;      // 4096 floats staging for W

    const int tid = threadIdx.x;
    const int out = tid & 127;
    const int row = tid >> 7;
    const int b   = blockIdx.x * 2 + row;

    // stage W_hh -> registers (4 coalesced passes through shared)
    unsigned long long w2[64];
    for (int p = 0; p < 4; ++p) {
        for (int i = tid; i < 32 * 128; i += 256)
            s_stg[i] = W_hh[p * 32 * 128 + i];
        __syncthreads();
        if ((out >> 5) == p) {
            const unsigned long long* wrow =
                (const unsigned long long*)(s_stg + (out & 31) * 128);
            #pragma unroll
            for (int k = 0; k < 64; ++k) w2[k] = wrow[k];
        }
        __syncthreads();
    }

    // init h buffer 0
    s_h[row * 128 + out] = h0[(size_t)b * HIDDEN + out];
    __syncthreads();

    const float* xp_me = g_xp + (size_t)b * HIDDEN + out;
    float xv_cur = xp_me[0];
    float h = 0.0f;

    for (int t = 0; t < TT; ++t) {
        float xv_next = (t + 1 < TT) ? xp_me[(size_t)(t + 1) * (BB * HIDDEN)] : 0.0f;

        const ulonglong2* h4 =
            (const ulonglong2*)(s_h + (t & 1) * 256 + row * 128);
        unsigned long long acc0 = 0, acc1 = 0, acc2a = 0, acc3 = 0;
        #pragma unroll
        for (int k4 = 0; k4 < 32; ++k4) {
            ulonglong2 a = h4[k4];
            if (k4 & 1) {
                acc2a = fma2(w2[k4 * 2],     a.x, acc2a);
                acc3  = fma2(w2[k4 * 2 + 1], a.y, acc3);
            } else {
                acc0  = fma2(w2[k4 * 2],     a.x, acc0);
                acc1  = fma2(w2[k4 * 2 + 1], a.y, acc1);
            }
        }
        float2 u0 = unpack2(acc0), u1 = unpack2(acc1);
        float2 u2 = unpack2(acc2a), u3 = unpack2(acc3);
        float s = ((u0.x + u0.y) + (u1.x + u1.y)) +
                  ((u2.x + u2.y) + (u3.x + u3.y)) + xv_cur;
        h = fast_tanh(s);
        s_h[((t + 1) & 1) * 256 + row * 128 + out] = h;
        xv_cur = xv_next;
        __syncthreads();
    }

    out_hidden[(size_t)b * HIDDEN + out] = h;
}

// ---------------------------------------------------------------------------
// Kernel 3: MLP head. One CTA per batch row.
// ---------------------------------------------------------------------------
__global__ void __launch_bounds__(256) head_kernel(
    const float* __restrict__ hidden, const float* __restrict__ W1,
    const float* __restrict__ b1, const float* __restrict__ W2,
    const float* __restrict__ b2, float* __restrict__ logits)
{
    __shared__ float shH[HIDDEN];
    __shared__ float shM[2 * HIDDEN];
    const int b = blockIdx.x, tid = threadIdx.x;
    if (tid < HIDDEN) shH[tid] = hidden[(size_t)b * HIDDEN + tid];
    __syncthreads();

    float acc = b1[tid];
    const float4* w4 = (const float4*)(W1 + (size_t)tid * HIDDEN);
    const float4* h4 = (const float4*)shH;
    #pragma unroll 8
    for (int k4 = 0; k4 < 32; ++k4) {
        float4 w = w4[k4];
        float4 h = h4[k4];
        acc = fmaf(w.x, h.x, acc);
        acc = fmaf(w.y, h.y, acc);
        acc = fmaf(w.z, h.z, acc);
        acc = fmaf(w.w, h.w, acc);
    }
    shM[tid] = fmaxf(acc, 0.0f);
    __syncthreads();

    if (tid < NCLASS) {
        float a = b2[tid];
        const float* w2 = W2 + (size_t)tid * (2 * HIDDEN);
        #pragma unroll 8
        for (int k = 0; k < 2 * HIDDEN; ++k)
            a = fmaf(shM[k], w2[k], a);
        logits[(size_t)b * NCLASS + tid] = a;
    }
}

// ---------------------------------------------------------------------------
extern "C" void kernel_launch(void* const* d_in, const int* in_sizes, int n_in,
                              void* d_out, int out_size)
{
    const int*   x    = (const int*)  d_in[0];
    const float* h0   = (const float*)d_in[1];
    const float* emb  = (const float*)d_in[2];
    const float* W_ih = (const float*)d_in[3];
    const float* W_hh = (const float*)d_in[4];
    const float* b_ih = (const float*)d_in[5];
    const float* b_hh = (const float*)d_in[6];
    const float* W1   = (const float*)d_in[7];
    const float* b1   = (const float*)d_in[8];
    const float* W2   = (const float*)d_in[9];
    const float* b2   = (const float*)d_in[10];

    float* out    = (float*)d_out;
    float* logits = out;                 // [256*4]
    float* hidden = out + BB * NCLASS;   // [256*128]

    const int smem1 = (896 + 2 * XP_CH * 128) * sizeof(float);  // ~20KB
    const int smem2 = (512 + 32 * 128) * sizeof(float);         // ~18.5KB

    xproj_kernel<<<XP_GRID, 256, smem1>>>(x, emb, W_ih, b_ih, b_hh);
    rnn_kernel<<<BB / 2, 256, smem2>>>(h0, W_hh, hidden);
    head_kernel<<<BB, 256>>>(hidden, W1, b1, W2, b2, logits);
}